// round 2
// baseline (speedup 1.0000x reference)
#include <cuda_runtime.h>
#include <cstdint>

// Problem constants (VectorQuantizer: inputs [32,64,64,64] NCHW, weight [512,64])
#define DIMD 64       // embedding dim
#define NCODE 512     // num embeddings
#define HW 4096       // 64*64 spatial
#define TPB 256       // threads per block, 1 vector per thread

// Device-global scratch (allocation-free per harness rules)
__device__ float g_wn[NCODE];      // ||w_k||^2
__device__ float g_psum[4096];     // per-block loss partial sums (>= max blocks)

// ---------------------------------------------------------------------------
// Kernel 0: per-code squared norms ||w_k||^2 (sequential d-order)
// ---------------------------------------------------------------------------
__global__ void vq_init_kernel(const float* __restrict__ w) {
    int k = blockIdx.x * blockDim.x + threadIdx.x;
    if (k < NCODE) {
        const float* row = w + k * DIMD;
        float s = 0.f;
#pragma unroll
        for (int d = 0; d < DIMD; d++) s += row[d] * row[d];
        g_wn[k] = s;
    }
}

// ---------------------------------------------------------------------------
// Kernel 1: main VQ — argmin over 512 codes + quantized write + loss partials
// One thread = one spatial vector. Weight lives in dynamic smem (128 KB).
// Inner product uses packed fma.rn.f32x2 (2 fp32 FMA / instruction).
// Distance replicates the reference rounding: fl(fl(A - fl(2B)) + wn).
// ---------------------------------------------------------------------------
__global__ void __launch_bounds__(TPB, 1)
vq_main_kernel(const float* __restrict__ in,
               const float* __restrict__ w,
               float* __restrict__ out_disc,
               float* __restrict__ out_q,
               int nvec)
{
    extern __shared__ float smem[];
    float* ws  = smem;            // [NCODE*DIMD] weight copy
    float* wns = smem + NCODE * DIMD;  // [NCODE] norms

    // Cooperative weight load (coalesced float4)
    {
        const float4* src = reinterpret_cast<const float4*>(w);
        float4* dst = reinterpret_cast<float4*>(ws);
        for (int i = threadIdx.x; i < (NCODE * DIMD) / 4; i += TPB) dst[i] = src[i];
        for (int i = threadIdx.x; i < NCODE; i += TPB) wns[i] = g_wn[i];
    }
    __syncthreads();

    const int vec = blockIdx.x * TPB + threadIdx.x;
    const bool active = (vec < nvec);

    // Load this thread's vector (NCHW: stride HW between channels), pack pairs
    unsigned long long xp[DIMD / 2];
    float A = 0.f;   // ||x||^2, sequential d-order (whole-ulp shifts are harmless)
    int bi = 0;
    float best;

    if (active) {
        const int b  = vec >> 12;        // vec / HW
        const int hw = vec & (HW - 1);
        const float* xb = in + ((size_t)b * DIMD) * HW + hw;
#pragma unroll
        for (int j = 0; j < DIMD / 2; j++) {
            float a0 = xb[(size_t)(2 * j)     * HW];
            float a1 = xb[(size_t)(2 * j + 1) * HW];
            A += a0 * a0;
            A += a1 * a1;
            xp[j] = ((unsigned long long)__float_as_uint(a1) << 32) | __float_as_uint(a0);
        }
        best = __int_as_float(0x7f7fffff); // FLT_MAX

        // ---- distance scan over 512 codes ----
#pragma unroll 2
        for (int k = 0; k < NCODE; k++) {
            const ulonglong2* wr =
                reinterpret_cast<const ulonglong2*>(ws + (k << 6));
            unsigned long long acc0 = 0ull, acc1 = 0ull; // two +0.0f each
#pragma unroll
            for (int i = 0; i < 16; i++) {
                ulonglong2 wv = wr[i];   // LDS.128 broadcast, conflict-free
                asm("fma.rn.f32x2 %0, %1, %2, %0;" : "+l"(acc0)
                    : "l"(xp[2 * i]),     "l"(wv.x));
                asm("fma.rn.f32x2 %0, %1, %2, %0;" : "+l"(acc1)
                    : "l"(xp[2 * i + 1]), "l"(wv.y));
            }
            float b0 = __uint_as_float((unsigned)acc0)
                     + __uint_as_float((unsigned)(acc0 >> 32));
            float b1 = __uint_as_float((unsigned)acc1)
                     + __uint_as_float((unsigned)(acc1 >> 32));
            float Bv = b0 + b1;                     // fp32 dot, err ~1e-9
            float dist = (A - (Bv + Bv)) + wns[k];  // replicate reference rounding
            if (dist < best) { best = dist; bi = k; }  // strict <: first-min tie
        }
    }

    // ---- epilogue: outputs + loss partial ----
    float ls = 0.f;
    if (active) {
        out_disc[vec] = (float)bi;
        const int b  = vec >> 12;
        const int hw = vec & (HW - 1);
        float* qb = out_q + ((size_t)b * DIMD) * HW + hw;
        const float2* wrow = reinterpret_cast<const float2*>(w + bi * DIMD); // L2 hit
#pragma unroll
        for (int j = 0; j < DIMD / 2; j++) {
            float2 wv = wrow[j];
            float a0 = __uint_as_float((unsigned)xp[j]);
            float a1 = __uint_as_float((unsigned)(xp[j] >> 32));
            float d0 = wv.x - a0;
            float d1 = wv.y - a1;
            qb[(size_t)(2 * j)     * HW] = a0 + d0;   // x + (q - x), straight-through
            qb[(size_t)(2 * j + 1) * HW] = a1 + d1;
            ls += d0 * d0;
            ls += d1 * d1;
        }
    }

    // Deterministic block reduction of loss (reuse smem after barrier)
    __syncthreads();
    float* red = smem;
    red[threadIdx.x] = ls;
    __syncthreads();
#pragma unroll
    for (int s = TPB / 2; s > 0; s >>= 1) {
        if (threadIdx.x < s) red[threadIdx.x] += red[threadIdx.x + s];
        __syncthreads();
    }
    if (threadIdx.x == 0) g_psum[blockIdx.x] = red[0];
}

// ---------------------------------------------------------------------------
// Kernel 2: deterministic final loss = m + 0.25*m, m = sum(diff^2)/total
// ---------------------------------------------------------------------------
__global__ void vq_final_kernel(float* __restrict__ out_loss, int nblk, float inv_total) {
    if (threadIdx.x == 0 && blockIdx.x == 0) {
        float s = 0.f;
        for (int i = 0; i < nblk; i++) s += g_psum[i];
        float m = s * inv_total;
        out_loss[0] = m + 0.25f * m;
    }
}

// ---------------------------------------------------------------------------
extern "C" void kernel_launch(void* const* d_in, const int* in_sizes, int n_in,
                              void* d_out, int out_size)
{
    const float* in = (const float*)d_in[0];   // [32,64,64,64] fp32
    const float* w  = (const float*)d_in[1];   // [512,64] fp32

    const int n_elems = in_sizes[0];           // 8388608
    const int nvec    = n_elems / DIMD;        // 131072
    const int nblk    = (nvec + TPB - 1) / TPB;

    float* out       = (float*)d_out;
    float* out_disc  = out;                    // [nvec]
    float* out_q     = out + nvec;             // [n_elems]
    float* out_loss  = out + nvec + n_elems;   // [1]

    static bool attr_set = false;
    const size_t smem_bytes = (NCODE * DIMD + NCODE) * sizeof(float);
    if (!attr_set) {
        cudaFuncSetAttribute(vq_main_kernel,
                             cudaFuncAttributeMaxDynamicSharedMemorySize,
                             (int)smem_bytes);
        attr_set = true;
    }

    vq_init_kernel<<<(NCODE + 255) / 256, 256>>>(w);
    vq_main_kernel<<<nblk, TPB, smem_bytes>>>(in, w, out_disc, out_q, nvec);
    vq_final_kernel<<<1, 32>>>(out_loss, nblk, 1.0f / (float)n_elems);
}

// round 3
// speedup vs baseline: 1.0924x; 1.0924x over previous
#include <cuda_runtime.h>
#include <cstdint>

// Problem constants (VectorQuantizer: inputs [32,64,64,64] NCHW, weight [512,64])
#define DIMD 64       // embedding dim
#define NCODE 512     // num embeddings
#define HW 4096       // 64*64 spatial
#define TPB 512       // threads per block
#define GRID 148      // persistent grid = #SMs (B300/GB300)
#define NVEC 131072   // 32*64*64
#define NTILE 2       // ceil(NVEC / (GRID*TPB))

// Device-global scratch (allocation-free per harness rules)
__device__ float g_wn[NCODE];      // ||w_k||^2
__device__ float g_psum[GRID];     // per-block loss partial sums

// ---------------------------------------------------------------------------
// Kernel 0: per-code squared norms ||w_k||^2 (sequential d-order)
// ---------------------------------------------------------------------------
__global__ void vq_init_kernel(const float* __restrict__ w) {
    int k = blockIdx.x * blockDim.x + threadIdx.x;
    if (k < NCODE) {
        const float* row = w + k * DIMD;
        float s = 0.f;
#pragma unroll
        for (int d = 0; d < DIMD; d++) s += row[d] * row[d];
        g_wn[k] = s;
    }
}

// ---------------------------------------------------------------------------
// Kernel 1: persistent VQ — each block stages the full codebook in smem ONCE,
// then loops over NTILE vector tiles. One thread = one vector per tile.
// Inner product uses packed fma.rn.f32x2 (FFMA2: 2 fp32 MACs / inst).
// Distance replicates the reference rounding: fl(fl(A - fl(2B)) + wn).
// ---------------------------------------------------------------------------
__global__ void __launch_bounds__(TPB, 1)
vq_main_kernel(const float* __restrict__ in,
               const float* __restrict__ w,
               float* __restrict__ out_disc,
               float* __restrict__ out_q)
{
    extern __shared__ float smem[];
    float* ws  = smem;                 // [NCODE*DIMD] weight copy
    float* wns = smem + NCODE * DIMD;  // [NCODE] norms

    // Cooperative weight load (coalesced float4), once per block lifetime
    {
        const float4* src = reinterpret_cast<const float4*>(w);
        float4* dst = reinterpret_cast<float4*>(ws);
        for (int i = threadIdx.x; i < (NCODE * DIMD) / 4; i += TPB) dst[i] = src[i];
        for (int i = threadIdx.x; i < NCODE; i += TPB) wns[i] = g_wn[i];
    }
    __syncthreads();

    float ls = 0.f;  // loss partial accumulated across tiles

#pragma unroll
    for (int t = 0; t < NTILE; t++) {
        const int vec = t * (GRID * TPB) + blockIdx.x * TPB + threadIdx.x;
        if (vec < NVEC) {
            const int b  = vec >> 12;        // vec / HW
            const int hw = vec & (HW - 1);
            const float* xb = in + ((size_t)b * DIMD) * HW + hw;

            // Load vector (NCHW channel stride = HW), pack into f32x2 pairs
            unsigned long long xp[DIMD / 2];
            float A = 0.f;
#pragma unroll
            for (int j = 0; j < DIMD / 2; j++) {
                float a0 = xb[(size_t)(2 * j)     * HW];
                float a1 = xb[(size_t)(2 * j + 1) * HW];
                A += a0 * a0;
                A += a1 * a1;
                xp[j] = ((unsigned long long)__float_as_uint(a1) << 32)
                      | __float_as_uint(a0);
            }

            float best = __int_as_float(0x7f7fffff); // FLT_MAX
            int bi = 0;

            // ---- distance scan over 512 codes ----
#pragma unroll 2
            for (int k = 0; k < NCODE; k++) {
                const ulonglong2* wr =
                    reinterpret_cast<const ulonglong2*>(ws + (k << 6));
                unsigned long long acc0 = 0ull, acc1 = 0ull; // packed +0.0f pairs
#pragma unroll
                for (int i = 0; i < 16; i++) {
                    ulonglong2 wv = wr[i];   // LDS.128 broadcast, conflict-free
                    asm("fma.rn.f32x2 %0, %1, %2, %0;" : "+l"(acc0)
                        : "l"(xp[2 * i]),     "l"(wv.x));
                    asm("fma.rn.f32x2 %0, %1, %2, %0;" : "+l"(acc1)
                        : "l"(xp[2 * i + 1]), "l"(wv.y));
                }
                float b0 = __uint_as_float((unsigned)acc0)
                         + __uint_as_float((unsigned)(acc0 >> 32));
                float b1 = __uint_as_float((unsigned)acc1)
                         + __uint_as_float((unsigned)(acc1 >> 32));
                float Bv = b0 + b1;                      // fp32 dot, err ~1e-9
                float dist = fmaf(-2.0f, Bv, A) + wns[k]; // fl(A-2B)+wn (ref rounding)
                if (dist < best) { best = dist; bi = k; } // strict <: first-min tie
            }

            // ---- epilogue: outputs + loss partial ----
            out_disc[vec] = (float)bi;
            float* qb = out_q + ((size_t)b * DIMD) * HW + hw;
            const float2* wrow = reinterpret_cast<const float2*>(w + bi * DIMD);
#pragma unroll
            for (int j = 0; j < DIMD / 2; j++) {
                float2 wv = wrow[j];
                float a0 = __uint_as_float((unsigned)xp[j]);
                float a1 = __uint_as_float((unsigned)(xp[j] >> 32));
                float d0 = wv.x - a0;
                float d1 = wv.y - a1;
                qb[(size_t)(2 * j)     * HW] = a0 + d0;  // x + (q-x), straight-through
                qb[(size_t)(2 * j + 1) * HW] = a1 + d1;
                ls += d0 * d0;
                ls += d1 * d1;
            }
        }
    }

    // Deterministic block reduction of loss (reuse smem after barrier)
    __syncthreads();
    float* red = smem;
    red[threadIdx.x] = ls;
    __syncthreads();
#pragma unroll
    for (int s = TPB / 2; s > 0; s >>= 1) {
        if (threadIdx.x < s) red[threadIdx.x] += red[threadIdx.x + s];
        __syncthreads();
    }
    if (threadIdx.x == 0) g_psum[blockIdx.x] = red[0];
}

// ---------------------------------------------------------------------------
// Kernel 2: deterministic final loss = m + 0.25*m, m = sum(diff^2)/total
// ---------------------------------------------------------------------------
__global__ void vq_final_kernel(float* __restrict__ out_loss, float inv_total) {
    if (threadIdx.x == 0 && blockIdx.x == 0) {
        float s = 0.f;
        for (int i = 0; i < GRID; i++) s += g_psum[i];
        float m = s * inv_total;
        out_loss[0] = m + 0.25f * m;
    }
}

// ---------------------------------------------------------------------------
extern "C" void kernel_launch(void* const* d_in, const int* in_sizes, int n_in,
                              void* d_out, int out_size)
{
    const float* in = (const float*)d_in[0];   // [32,64,64,64] fp32
    const float* w  = (const float*)d_in[1];   // [512,64] fp32

    const int n_elems = in_sizes[0];           // 8388608
    const int nvec    = n_elems / DIMD;        // 131072

    float* out       = (float*)d_out;
    float* out_disc  = out;                    // [nvec]
    float* out_q     = out + nvec;             // [n_elems]
    float* out_loss  = out + nvec + n_elems;   // [1]

    static bool attr_set = false;
    const size_t smem_bytes = (NCODE * DIMD + NCODE) * sizeof(float);
    if (!attr_set) {
        cudaFuncSetAttribute(vq_main_kernel,
                             cudaFuncAttributeMaxDynamicSharedMemorySize,
                             (int)smem_bytes);
        attr_set = true;
    }

    vq_init_kernel<<<(NCODE + 255) / 256, 256>>>(w);
    vq_main_kernel<<<GRID, TPB, smem_bytes>>>(in, w, out_disc, out_q);
    vq_final_kernel<<<1, 32>>>(out_loss, 1.0f / (float)n_elems);
}

// round 4
// speedup vs baseline: 1.0995x; 1.0065x over previous
#include <cuda_runtime.h>
#include <cstdint>

// Problem constants (VectorQuantizer: inputs [32,64,64,64] NCHW, weight [512,64])
#define DIMD 64       // embedding dim
#define NCODE 512     // num embeddings
#define HW 4096       // 64*64 spatial
#define TPB 512       // threads per block
#define GRID 148      // persistent grid = #SMs (B300/GB300)
#define NVEC 131072   // 32*64*64
#define NTILE 2       // ceil(NVEC / (GRID*TPB))

// Device-global scratch (allocation-free per harness rules)
__device__ float g_wn[NCODE];      // ||w_k||^2
__device__ float g_psum[GRID];     // per-block loss partial sums

// ---------------------------------------------------------------------------
// Kernel 0: per-code squared norms ||w_k||^2 (sequential d-order)
// ---------------------------------------------------------------------------
__global__ void vq_init_kernel(const float* __restrict__ w) {
    int k = blockIdx.x * blockDim.x + threadIdx.x;
    if (k < NCODE) {
        const float* row = w + k * DIMD;
        float s = 0.f;
#pragma unroll
        for (int d = 0; d < DIMD; d++) s += row[d] * row[d];
        g_wn[k] = s;
    }
}

// ---------------------------------------------------------------------------
// Kernel 1: persistent VQ — each block stages the full codebook in smem ONCE,
// then loops over NTILE vector tiles. One thread = one vector per tile.
// Inner product uses packed fma.rn.f32x2 (FFMA2: 2 fp32 MACs / inst).
// Distance replicates the reference rounding: fl(fl(A - fl(2B)) + wn).
// ---------------------------------------------------------------------------
__global__ void __launch_bounds__(TPB, 1)
vq_main_kernel(const float* __restrict__ in,
               const float* __restrict__ w,
               float* __restrict__ out_disc,
               float* __restrict__ out_q)
{
    extern __shared__ float smem[];
    float* ws  = smem;                 // [NCODE*DIMD] weight copy
    float* wns = smem + NCODE * DIMD;  // [NCODE] norms

    // Cooperative weight load (coalesced float4), once per block lifetime
    {
        const float4* src = reinterpret_cast<const float4*>(w);
        float4* dst = reinterpret_cast<float4*>(ws);
        for (int i = threadIdx.x; i < (NCODE * DIMD) / 4; i += TPB) dst[i] = src[i];
        for (int i = threadIdx.x; i < NCODE; i += TPB) wns[i] = g_wn[i];
    }
    __syncthreads();

    float ls = 0.f;  // loss partial accumulated across tiles

#pragma unroll
    for (int t = 0; t < NTILE; t++) {
        const int vec = t * (GRID * TPB) + blockIdx.x * TPB + threadIdx.x;
        if (vec < NVEC) {
            const int b  = vec >> 12;        // vec / HW
            const int hw = vec & (HW - 1);
            const float* xb = in + ((size_t)b * DIMD) * HW + hw;

            // Load vector (NCHW channel stride = HW), pack into f32x2 pairs
            unsigned long long xp[DIMD / 2];
            float A = 0.f;
#pragma unroll
            for (int j = 0; j < DIMD / 2; j++) {
                float a0 = xb[(size_t)(2 * j)     * HW];
                float a1 = xb[(size_t)(2 * j + 1) * HW];
                A += a0 * a0;
                A += a1 * a1;
                xp[j] = ((unsigned long long)__float_as_uint(a1) << 32)
                      | __float_as_uint(a0);
            }

            float best = __int_as_float(0x7f7fffff); // FLT_MAX
            int bi = 0;

            // ---- distance scan over 512 codes ----
#pragma unroll 2
            for (int k = 0; k < NCODE; k++) {
                const ulonglong2* wr =
                    reinterpret_cast<const ulonglong2*>(ws + (k << 6));
                unsigned long long acc0 = 0ull, acc1 = 0ull; // packed +0.0f pairs
#pragma unroll
                for (int i = 0; i < 16; i++) {
                    ulonglong2 wv = wr[i];   // LDS.128 broadcast, conflict-free
                    asm("fma.rn.f32x2 %0, %1, %2, %0;" : "+l"(acc0)
                        : "l"(xp[2 * i]),     "l"(wv.x));
                    asm("fma.rn.f32x2 %0, %1, %2, %0;" : "+l"(acc1)
                        : "l"(xp[2 * i + 1]), "l"(wv.y));
                }
                float b0 = __uint_as_float((unsigned)acc0)
                         + __uint_as_float((unsigned)(acc0 >> 32));
                float b1 = __uint_as_float((unsigned)acc1)
                         + __uint_as_float((unsigned)(acc1 >> 32));
                float Bv = b0 + b1;                      // fp32 dot, err ~1e-9
                float dist = fmaf(-2.0f, Bv, A) + wns[k]; // fl(A-2B)+wn (ref rounding)
                if (dist < best) { best = dist; bi = k; } // strict <: first-min tie
            }

            // ---- epilogue: outputs + loss partial ----
            out_disc[vec] = (float)bi;
            float* qb = out_q + ((size_t)b * DIMD) * HW + hw;
            const float2* wrow = reinterpret_cast<const float2*>(w + bi * DIMD);
#pragma unroll
            for (int j = 0; j < DIMD / 2; j++) {
                float2 wv = wrow[j];
                float a0 = __uint_as_float((unsigned)xp[j]);
                float a1 = __uint_as_float((unsigned)(xp[j] >> 32));
                float d0 = wv.x - a0;
                float d1 = wv.y - a1;
                qb[(size_t)(2 * j)     * HW] = a0 + d0;  // x + (q-x), straight-through
                qb[(size_t)(2 * j + 1) * HW] = a1 + d1;
                ls += d0 * d0;
                ls += d1 * d1;
            }
        }
    }

    // Deterministic block reduction of loss (reuse smem after barrier)
    __syncthreads();
    float* red = smem;
    red[threadIdx.x] = ls;
    __syncthreads();
#pragma unroll
    for (int s = TPB / 2; s > 0; s >>= 1) {
        if (threadIdx.x < s) red[threadIdx.x] += red[threadIdx.x + s];
        __syncthreads();
    }
    if (threadIdx.x == 0) g_psum[blockIdx.x] = red[0];
}

// ---------------------------------------------------------------------------
// Kernel 2: deterministic final loss = m + 0.25*m, m = sum(diff^2)/total
// ---------------------------------------------------------------------------
__global__ void vq_final_kernel(float* __restrict__ out_loss, float inv_total) {
    if (threadIdx.x == 0 && blockIdx.x == 0) {
        float s = 0.f;
        for (int i = 0; i < GRID; i++) s += g_psum[i];
        float m = s * inv_total;
        out_loss[0] = m + 0.25f * m;
    }
}

// ---------------------------------------------------------------------------
extern "C" void kernel_launch(void* const* d_in, const int* in_sizes, int n_in,
                              void* d_out, int out_size)
{
    const float* in = (const float*)d_in[0];   // [32,64,64,64] fp32
    const float* w  = (const float*)d_in[1];   // [512,64] fp32

    const int n_elems = in_sizes[0];           // 8388608
    const int nvec    = n_elems / DIMD;        // 131072

    float* out       = (float*)d_out;
    float* out_disc  = out;                    // [nvec]
    float* out_q     = out + nvec;             // [n_elems]
    float* out_loss  = out + nvec + n_elems;   // [1]

    static bool attr_set = false;
    const size_t smem_bytes = (NCODE * DIMD + NCODE) * sizeof(float);
    if (!attr_set) {
        cudaFuncSetAttribute(vq_main_kernel,
                             cudaFuncAttributeMaxDynamicSharedMemorySize,
                             (int)smem_bytes);
        attr_set = true;
    }

    vq_init_kernel<<<(NCODE + 255) / 256, 256>>>(w);
    vq_main_kernel<<<GRID, TPB, smem_bytes>>>(in, w, out_disc, out_q);
    vq_final_kernel<<<1, 32>>>(out_loss, 1.0f / (float)n_elems);
}